// round 16
// baseline (speedup 1.0000x reference)
#include <cuda_runtime.h>
#include <cuda_bf16.h>
#include <math.h>
#include <stdint.h>

// ---------------------------------------------------------------------------
// Problem constants
// ---------------------------------------------------------------------------
#define DM   512
#define FFD  2048
#define NB   8
#define TQ   512
#define TKV  4096
#define MQ   (NB*TQ)    // 4096
#define MKV  (NB*TKV)   // 32768

// ---------------------------------------------------------------------------
// Scratch
// ---------------------------------------------------------------------------
#define DEVBF __device__ __align__(256) __nv_bfloat16
DEVBF g_qn_h [(size_t)MQ*DM];                              // LN(query) hi
DEVBF g_kvn_h[(size_t)MKV*DM];                             // LN(kv) hi
DEVBF g_q_h  [(size_t)MQ*DM];                              // q proj hi
DEVBF g_k_h  [(size_t)MKV*DM];                             // k proj hi
DEVBF g_qp_h [(size_t)MQ*DM];                              // query_pos hi
DEVBF g_kp_h [(size_t)MKV*DM];                             // key_pos hi
DEVBF g_vt_h [(size_t)DM*MKV];                             // v proj transposed hi
DEVBF g_sc_h [(size_t)NB*TQ*TKV];                          // bf16 logits
DEVBF g_at_h [(size_t)NB*TQ*TKV];                          // softmax probs hi
DEVBF g_xn_h [(size_t)MQ*DM],   g_xn_l [(size_t)MQ*DM];    // LN(attnout) h/l
DEVBF g_wq_h [(size_t)DM*DM];                              // Wq^T hi
DEVBF g_wk_h [(size_t)DM*DM];
DEVBF g_wv_h [(size_t)DM*DM];
DEVBF g_wi_h [(size_t)DM*FFD],  g_wi_l [(size_t)DM*FFD];   // W_inner (row-major) h/l
DEVBF g_wp_h [(size_t)DM*FFD],  g_wp_l [(size_t)DM*FFD];   // W_proj^T [512,2048] h/l
DEVBF g_mt_h [(size_t)DM*DM],   g_mt_l [(size_t)DM*DM];    // MT = (Wi@Wp)^T h/l
__device__ float g_c[DM];                      // folded bias: b_inner@Wp + b_proj
__device__ float g_ao [(size_t)MQ*DM];         // attn out + residual
__device__ float g_xnf[(size_t)MQ*DM];         // LN(attnout) fp32

// ---------------------------------------------------------------------------
// helpers
// ---------------------------------------------------------------------------
__device__ __forceinline__ uint32_t smem_u32(const void* p) {
    uint32_t a;
    asm("{ .reg .u64 t; cvta.to.shared.u64 t, %1; cvt.u32.u64 %0, t; }"
        : "=r"(a) : "l"(p));
    return a;
}
__device__ __forceinline__ void ldm4(uint32_t* r, uint32_t addr) {
    asm volatile("ldmatrix.sync.aligned.m8n8.x4.shared.b16 {%0,%1,%2,%3}, [%4];"
        : "=r"(r[0]), "=r"(r[1]), "=r"(r[2]), "=r"(r[3]) : "r"(addr));
}
__device__ __forceinline__ void mma_bf16(float* c, const uint32_t* a,
                                         uint32_t b0, uint32_t b1) {
    asm volatile(
        "mma.sync.aligned.m16n8k16.row.col.f32.bf16.bf16.f32 "
        "{%0,%1,%2,%3}, {%4,%5,%6,%7}, {%8,%9}, {%0,%1,%2,%3};"
        : "+f"(c[0]), "+f"(c[1]), "+f"(c[2]), "+f"(c[3])
        : "r"(a[0]), "r"(a[1]), "r"(a[2]), "r"(a[3]), "r"(b0), "r"(b1));
}
__device__ __forceinline__ void bsplit(float x, __nv_bfloat16& h, __nv_bfloat16& l) {
    h = __float2bfloat16(x);
    l = __float2bfloat16(x - __bfloat162float(h));
}
#define CPA(dst, src) \
    asm volatile("cp.async.cg.shared.global [%0], [%1], 16;" :: "r"(dst), "l"(src))
#define CPCOMMIT() asm volatile("cp.async.commit_group;" ::: "memory")
#define CPWAIT(n)  asm volatile("cp.async.wait_group %0;" :: "n"(n) : "memory")

#define ROWB   80      // bytes per smem row (32 bf16 + pad), conflict-free ldmatrix
#define NSTG   3

// ---------------------------------------------------------------------------
// bf16 MMA GEMM.
//   NPASS: 1 = hh;  3 = hh + lh + hl (fp32-grade)
//   OUT_MODE: 0=fp32 C, 1=bf16 h/l planes, 3=bf16 hi plane, 4=transposed hi
//   BM=128 everywhere; 1-pass kernels run 2 CTAs/SM.
// ---------------------------------------------------------------------------
template<int BM, int NPASS, bool DUAL, int OUT_MODE, bool HAS_BIAS, bool HAS_RES, bool HAS_SCALE>
__global__ void __launch_bounds__(BM*2, (BM==128 && NPASS==1) ? 2 : 1)
mma_gemm(const __nv_bfloat16* __restrict__ Ah, const __nv_bfloat16* __restrict__ Al,
         const __nv_bfloat16* __restrict__ Bh, const __nv_bfloat16* __restrict__ Bl,
         const __nv_bfloat16* __restrict__ A2h, const __nv_bfloat16* __restrict__ A2l,
         const __nv_bfloat16* __restrict__ B2h, const __nv_bfloat16* __restrict__ B2l,
         const float* __restrict__ bias, const float* __restrict__ res,
         float* __restrict__ Cf, __nv_bfloat16* __restrict__ Ch, __nv_bfloat16* __restrict__ Cl,
         int N, int K, int lda, int ldb, int ldct,
         long long zA, long long zB, long long zC, long long zRes, float scale)
{
    constexpr int PLA = (NPASS >= 2) ? 2 : 1;
    constexpr int PLB = (NPASS == 3) ? 2 : 1;
    constexpr int PA = BM * ROWB;
    constexpr int PB = 128 * ROWB;
    constexpr int STAGE = PLA * PA + PLB * PB;

    extern __shared__ char dsm[];
    const uint32_t sb = smem_u32(dsm);
    const int t = threadIdx.x, wid = t >> 5, lane = t & 31;
    const int wm = wid >> 2, wn = wid & 3;

    const long long bz = blockIdx.z;
    Ah += bz * zA; Bh += bz * zB;
    if (NPASS >= 2) Al += bz * zA;
    if (NPASS == 3) Bl += bz * zB;
    if (DUAL) { A2h += bz * zA; B2h += bz * zB; }
    if (HAS_RES) res += bz * zRes;
    if (OUT_MODE == 0) Cf += bz * zC;
    if (OUT_MODE == 3) Ch += bz * zC;   // batched bf16-hi output (scores)

    const int m0 = blockIdx.y * BM;
    const int n0 = blockIdx.x * 128;

    float acc[4][4][4];
    #pragma unroll
    for (int i = 0; i < 4; i++)
        #pragma unroll
        for (int j = 0; j < 4; j++)
            #pragma unroll
            for (int e = 0; e < 4; e++) acc[i][j][e] = 0.0f;

    const int r8 = lane & 7, sel = lane >> 3;
    const uint32_t aOff = (uint32_t)((wm * 64 + (sel & 1) * 8 + r8) * ROWB + ((sel >> 1) * 8) * 2);
    const uint32_t bOff = (uint32_t)((wn * 32 + (sel >> 1) * 8 + r8) * ROWB + ((sel & 1) * 8) * 2);

    const int lrow = t >> 1;
    const int lcol = (t & 1) * 32;

    const int kt = K / 32;
    const int nt = DUAL ? 2 * kt : kt;

#define CPLOAD(ii, stg_) do {                                                    \
        const int pr_ = (DUAL && (ii) >= kt) ? 1 : 0;                            \
        const int k0_ = ((ii) - pr_ * kt) * 32;                                  \
        const uint32_t sd = sb + (stg_) * STAGE + lrow * ROWB + lcol;            \
        const char* gA = (const char*)((pr_ ? A2h : Ah) + (size_t)(m0 + lrow) * lda + k0_) + lcol; \
        CPA(sd, gA);  CPA(sd + 16, gA + 16);                                     \
        if (NPASS >= 2) {                                                        \
            const char* ga = (const char*)((pr_ ? A2h : Al) + (size_t)(m0 + lrow) * lda + k0_) + lcol; \
            CPA(sd + PA, ga);  CPA(sd + PA + 16, ga + 16);                       \
        }                                                                        \
        if (t < 256) {                                                           \
            const char* gB = (const char*)((pr_ ? B2h : Bh) + (size_t)(n0 + lrow) * ldb + k0_) + lcol; \
            CPA(sd + PLA * PA, gB);  CPA(sd + PLA * PA + 16, gB + 16);           \
            if (NPASS == 3) {                                                    \
                const char* gb = (const char*)((pr_ ? B2h : Bl) + (size_t)(n0 + lrow) * ldb + k0_) + lcol; \
                CPA(sd + PLA * PA + PB, gb);  CPA(sd + PLA * PA + PB + 16, gb + 16); \
            }                                                                    \
        }                                                                        \
        CPCOMMIT();                                                              \
    } while (0)

    CPLOAD(0, 0);
    CPLOAD(1, 1);

    int stg = 0;
    #pragma unroll 1
    for (int tt = 0; tt < nt; ++tt) {
        if (tt + 1 < nt) CPWAIT(1); else CPWAIT(0);
        __syncthreads();
        if (tt + 2 < nt) {
            const int ns = (stg + 2 >= NSTG) ? stg + 2 - NSTG : stg + 2;
            CPLOAD(tt + 2, ns);
        }

        const uint32_t sbase = sb + stg * STAGE;
        #pragma unroll
        for (int ks = 0; ks < 2; ++ks) {
            const uint32_t kso = ks * 32;
            uint32_t bh[2][4], bl[2][4];
            #pragma unroll
            for (int bi = 0; bi < 2; bi++) {
                ldm4(bh[bi], sbase + PLA * PA + bOff + bi * (16 * ROWB) + kso);
                if (NPASS == 3)
                    ldm4(bl[bi], sbase + PLA * PA + PB + bOff + bi * (16 * ROWB) + kso);
            }
            #pragma unroll
            for (int mi = 0; mi < 4; mi++) {
                uint32_t ah[4], al[4];
                ldm4(ah, sbase + aOff + mi * (16 * ROWB) + kso);
                if (NPASS >= 2)
                    ldm4(al, sbase + PA + aOff + mi * (16 * ROWB) + kso);
                #pragma unroll
                for (int ni = 0; ni < 4; ni++) {
                    const int bi = ni >> 1, sub = (ni & 1) * 2;
                    mma_bf16(acc[mi][ni], ah, bh[bi][sub], bh[bi][sub + 1]);      // hh
                    if (NPASS >= 2)
                        mma_bf16(acc[mi][ni], al, bh[bi][sub], bh[bi][sub + 1]);  // lh
                    if (NPASS == 3)
                        mma_bf16(acc[mi][ni], ah, bl[bi][sub], bl[bi][sub + 1]);  // hl
                }
            }
        }
        stg = (stg + 1 == NSTG) ? 0 : stg + 1;
    }
#undef CPLOAD

    // ---------------- epilogue ----------------
    const int qr = lane >> 2;
    const int qc = (lane & 3) * 2;

    if (OUT_MODE == 4) {
        __syncthreads();
        __nv_bfloat16* sth = (__nv_bfloat16*)dsm;
        #pragma unroll
        for (int mi = 0; mi < 4; mi++)
            #pragma unroll
            for (int ni = 0; ni < 4; ni++)
                #pragma unroll
                for (int h = 0; h < 2; h++)
                    #pragma unroll
                    for (int e = 0; e < 2; e++) {
                        const int ml = wm * 64 + mi * 16 + qr + h * 8;
                        const int nl = wn * 32 + ni * 8 + qc + e;
                        float v = acc[mi][ni][h * 2 + e];
                        if (HAS_BIAS) v += bias[n0 + nl];
                        sth[nl * 136 + ml] = __float2bfloat16(v);
                    }
        __syncthreads();
        for (int i = t; i < 128 * 16; i += BM * 2) {
            const int row = i >> 4, seg = i & 15;
            const size_t go = (size_t)(n0 + row) * ldct + m0 + seg * 8;
            *(uint4*)(Ch + go) = *(uint4*)(sth + row * 136 + seg * 8);
        }
        return;
    }

    #pragma unroll
    for (int mi = 0; mi < 4; mi++)
        #pragma unroll
        for (int ni = 0; ni < 4; ni++) {
            const int row = m0 + wm * 64 + mi * 16 + qr;
            const int col = n0 + wn * 32 + ni * 8 + qc;
            float2 bb = make_float2(0.f, 0.f);
            if (HAS_BIAS) bb = *(const float2*)(bias + col);
            #pragma unroll
            for (int h = 0; h < 2; h++) {
                const int rr = row + h * 8;
                float2 o = make_float2(acc[mi][ni][h * 2], acc[mi][ni][h * 2 + 1]);
                if (HAS_SCALE) { o.x *= scale; o.y *= scale; }
                if (HAS_BIAS)  { o.x += bb.x; o.y += bb.y; }
                if (OUT_MODE == 0) {
                    if (HAS_RES) {
                        float2 rv = *(const float2*)(res + (size_t)rr * N + col);
                        o.x += rv.x; o.y += rv.y;
                    }
                    *(float2*)(Cf + (size_t)rr * N + col) = o;
                } else if (OUT_MODE == 1) {
                    __nv_bfloat16 h0, l0, h1, l1;
                    bsplit(o.x, h0, l0);
                    bsplit(o.y, h1, l1);
                    __nv_bfloat162 ph; ph.x = h0; ph.y = h1;
                    __nv_bfloat162 pl; pl.x = l0; pl.y = l1;
                    *(__nv_bfloat162*)(Ch + (size_t)rr * N + col) = ph;
                    *(__nv_bfloat162*)(Cl + (size_t)rr * N + col) = pl;
                } else { // OUT_MODE == 3
                    __nv_bfloat162 ph;
                    ph.x = __float2bfloat16(o.x);
                    ph.y = __float2bfloat16(o.y);
                    *(__nv_bfloat162*)(Ch + (size_t)rr * N + col) = ph;
                }
            }
        }
}

// ---------------------------------------------------------------------------
// LayerNorm (D=512) -> bf16 hi plane [+ lo plane] [+ fp32]
// ---------------------------------------------------------------------------
template<bool LO, bool F32OUT>
__global__ void ln_split_kernel(const float* __restrict__ x,
                                const float* __restrict__ g,
                                const float* __restrict__ b,
                                __nv_bfloat16* __restrict__ yh,
                                __nv_bfloat16* __restrict__ yl,
                                float* __restrict__ yf)
{
    __shared__ float sh[8];
    const size_t row = blockIdx.x;
    const int t = threadIdx.x;

    float4 v = ((const float4*)(x + row * DM))[t];
    float s  = v.x + v.y + v.z + v.w;
    float sq = v.x*v.x + v.y*v.y + v.z*v.z + v.w*v.w;
    #pragma unroll
    for (int o = 16; o > 0; o >>= 1) {
        s  += __shfl_down_sync(0xffffffffu, s,  o);
        sq += __shfl_down_sync(0xffffffffu, sq, o);
    }
    if ((t & 31) == 0) { sh[t >> 5] = s; sh[4 + (t >> 5)] = sq; }
    __syncthreads();
    const float S  = sh[0] + sh[1] + sh[2] + sh[3];
    const float SQ = sh[4] + sh[5] + sh[6] + sh[7];
    const float mu = S * (1.0f / DM);
    const float var = SQ * (1.0f / DM) - mu * mu;
    const float r = rsqrtf(var + 1e-6f);

    const float4 gg = ((const float4*)g)[t];
    const float4 bb = ((const float4*)b)[t];
    float o[4];
    o[0] = (v.x - mu) * r * gg.x + bb.x;
    o[1] = (v.y - mu) * r * gg.y + bb.y;
    o[2] = (v.z - mu) * r * gg.z + bb.z;
    o[3] = (v.w - mu) * r * gg.w + bb.w;

    __nv_bfloat16 h[4], l[4];
    #pragma unroll
    for (int j = 0; j < 4; j++) bsplit(o[j], h[j], l[j]);
    *(uint2*)(yh + row * DM + t * 4) = *(uint2*)h;
    if (LO) *(uint2*)(yl + row * DM + t * 4) = *(uint2*)l;
    if (F32OUT) *(float4*)(yf + row * DM + t * 4) = make_float4(o[0], o[1], o[2], o[3]);
}

// ---------------------------------------------------------------------------
// Elementwise fp32 -> bf16 hi plane (pos tensors)
// ---------------------------------------------------------------------------
__global__ void split_kernel(const float* __restrict__ x,
                             __nv_bfloat16* __restrict__ yh, size_t n4)
{
    const size_t i = (size_t)blockIdx.x * blockDim.x + threadIdx.x;
    if (i >= n4) return;
    float4 v = ((const float4*)x)[i];
    __nv_bfloat16 h[4];
    h[0] = __float2bfloat16(v.x); h[1] = __float2bfloat16(v.y);
    h[2] = __float2bfloat16(v.z); h[3] = __float2bfloat16(v.w);
    *(uint2*)(yh + i * 4) = *(uint2*)h;
}

// Elementwise fp32 -> bf16 hi + lo planes (W_inner)
__global__ void split2_kernel(const float* __restrict__ x,
                              __nv_bfloat16* __restrict__ yh,
                              __nv_bfloat16* __restrict__ yl, size_t n4)
{
    const size_t i = (size_t)blockIdx.x * blockDim.x + threadIdx.x;
    if (i >= n4) return;
    float4 v = ((const float4*)x)[i];
    __nv_bfloat16 h[4], l[4];
    bsplit(v.x, h[0], l[0]); bsplit(v.y, h[1], l[1]);
    bsplit(v.z, h[2], l[2]); bsplit(v.w, h[3], l[3]);
    *(uint2*)(yh + i * 4) = *(uint2*)h;
    *(uint2*)(yl + i * 4) = *(uint2*)l;
}

// ---------------------------------------------------------------------------
// W [K,N] fp32 -> WT hi [N,K] bf16 [+ lo]
// ---------------------------------------------------------------------------
template<bool LO>
__global__ void transpose_split_kernel(const float* __restrict__ W,
                                       __nv_bfloat16* __restrict__ Th,
                                       __nv_bfloat16* __restrict__ Tl,
                                       int K, int N)
{
    __shared__ float tile[32][33];
    const int n0 = blockIdx.x * 32, k0 = blockIdx.y * 32;
    const int tx = threadIdx.x, ty = threadIdx.y;
    #pragma unroll
    for (int i = 0; i < 32; i += 8)
        tile[ty + i][tx] = W[(size_t)(k0 + ty + i) * N + n0 + tx];
    __syncthreads();
    #pragma unroll
    for (int i = 0; i < 32; i += 8) {
        float v = tile[tx][ty + i];
        __nv_bfloat16 h, l;
        bsplit(v, h, l);
        Th[(size_t)(n0 + ty + i) * K + k0 + tx] = h;
        if (LO) Tl[(size_t)(n0 + ty + i) * K + k0 + tx] = l;
    }
}

// ---------------------------------------------------------------------------
// c = b_inner @ W_proj + b_proj
// ---------------------------------------------------------------------------
__global__ void bias_fold_kernel(const float* __restrict__ bi,
                                 const float* __restrict__ Wp,
                                 const float* __restrict__ bp,
                                 float* __restrict__ c)
{
    const int j = threadIdx.x;  // 512 threads
    float s = bp[j];
    for (int k = 0; k < FFD; k++) s += bi[k] * Wp[(size_t)k * DM + j];
    c[j] = s;
}

// ---------------------------------------------------------------------------
// Row softmax over TKV=4096, bf16 logits in -> bf16 probs out
// ---------------------------------------------------------------------------
__global__ void softmax_bf16_kernel(const __nv_bfloat16* __restrict__ S,
                                    __nv_bfloat16* __restrict__ Ah)
{
    __shared__ float sh[16];
    const size_t row = blockIdx.x;
    const __nv_bfloat16* p = S + row * (size_t)TKV;
    const int t = threadIdx.x;

    float v[16];
    #pragma unroll
    for (int i = 0; i < 4; i++) {
        uint2 u = ((const uint2*)p)[t + 256 * i];   // 4 bf16
        __nv_bfloat162 a = *(__nv_bfloat162*)&u.x;
        __nv_bfloat162 b = *(__nv_bfloat162*)&u.y;
        v[i*4+0] = __bfloat162float(a.x); v[i*4+1] = __bfloat162float(a.y);
        v[i*4+2] = __bfloat162float(b.x); v[i*4+3] = __bfloat162float(b.y);
    }

    float mx = -3.4e38f;
    #pragma unroll
    for (int i = 0; i < 16; i++) mx = fmaxf(mx, v[i]);
    #pragma unroll
    for (int o = 16; o > 0; o >>= 1) mx = fmaxf(mx, __shfl_xor_sync(0xffffffffu, mx, o));
    if ((t & 31) == 0) sh[t >> 5] = mx;
    __syncthreads();
    float m = sh[0];
    #pragma unroll
    for (int i = 1; i < 8; i++) m = fmaxf(m, sh[i]);

    float s = 0.0f;
    #pragma unroll
    for (int i = 0; i < 16; i++) { v[i] = __expf(v[i] - m); s += v[i]; }
    #pragma unroll
    for (int o = 16; o > 0; o >>= 1) s += __shfl_xor_sync(0xffffffffu, s, o);
    if ((t & 31) == 0) sh[8 + (t >> 5)] = s;
    __syncthreads();
    float tot = 0.0f;
    #pragma unroll
    for (int i = 0; i < 8; i++) tot += sh[8 + i];
    const float inv = 1.0f / tot;

    #pragma unroll
    for (int i = 0; i < 4; i++) {
        __nv_bfloat16 h[4];
        h[0] = __float2bfloat16(v[i*4+0] * inv);
        h[1] = __float2bfloat16(v[i*4+1] * inv);
        h[2] = __float2bfloat16(v[i*4+2] * inv);
        h[3] = __float2bfloat16(v[i*4+3] * inv);
        *(uint2*)(Ah + row * (size_t)TKV + (t + 256 * i) * 4) = *(uint2*)h;
    }
}

// ---------------------------------------------------------------------------
// Launcher (R15 topology; kproj & scores now BM=128, 2 CTAs/SM).
// Streams/events are statics created once on the first (uncaptured) call.
// ---------------------------------------------------------------------------
#define SYM(p, s) cudaGetSymbolAddress((void**)&p, s)
#define SM_K1_128 (NSTG * (128*ROWB + 128*ROWB))              // 61440
#define SM_K3_128 (NSTG * 2 * (128*ROWB + 128*ROWB))          // 122880

namespace {
struct GraphResources {
    cudaStream_t s1, s2;
    cudaEvent_t eFork, eWk, eKVN, eWv, eQside, eV, eMC;
    GraphResources() {
        cudaStreamCreateWithFlags(&s1, cudaStreamNonBlocking);
        cudaStreamCreateWithFlags(&s2, cudaStreamNonBlocking);
        cudaEventCreateWithFlags(&eFork, cudaEventDisableTiming);
        cudaEventCreateWithFlags(&eWk,   cudaEventDisableTiming);
        cudaEventCreateWithFlags(&eKVN,  cudaEventDisableTiming);
        cudaEventCreateWithFlags(&eWv,   cudaEventDisableTiming);
        cudaEventCreateWithFlags(&eQside,cudaEventDisableTiming);
        cudaEventCreateWithFlags(&eV,    cudaEventDisableTiming);
        cudaEventCreateWithFlags(&eMC,   cudaEventDisableTiming);
    }
};
} // namespace

extern "C" void kernel_launch(void* const* d_in, const int* in_sizes, int n_in,
                              void* d_out, int out_size)
{
    (void)in_sizes; (void)n_in; (void)out_size;
    const float* query     = (const float*)d_in[0];
    const float* key_value = (const float*)d_in[1];
    const float* query_pos = (const float*)d_in[2];
    const float* key_pos   = (const float*)d_in[3];
    const float* q_gamma   = (const float*)d_in[4];
    const float* q_beta    = (const float*)d_in[5];
    const float* kv_gamma  = (const float*)d_in[6];
    const float* kv_beta   = (const float*)d_in[7];
    const float* Wq        = (const float*)d_in[8];
    const float* bq        = (const float*)d_in[9];
    const float* Wk        = (const float*)d_in[10];
    const float* bk        = (const float*)d_in[11];
    const float* Wv        = (const float*)d_in[12];
    const float* bv        = (const float*)d_in[13];
    const float* ff_gamma  = (const float*)d_in[14];
    const float* ff_beta   = (const float*)d_in[15];
    const float* W_inner   = (const float*)d_in[16];
    const float* b_inner   = (const float*)d_in[17];
    const float* W_proj    = (const float*)d_in[18];
    const float* b_proj    = (const float*)d_in[19];
    float* out = (float*)d_out;

    __nv_bfloat16 *qnh,*kvnh,*qh,*kh,*qph,*kph,*vth,*sch,*ath,*xnh,*xnl;
    __nv_bfloat16 *wqh,*wkh,*wvh,*wih,*wil,*wph,*wpl,*mth,*mtl;
    float *ao,*xnf,*cfold;
    SYM(qnh,g_qn_h); SYM(kvnh,g_kvn_h);
    SYM(qh,g_q_h); SYM(kh,g_k_h);
    SYM(qph,g_qp_h); SYM(kph,g_kp_h);
    SYM(vth,g_vt_h); SYM(sch,g_sc_h); SYM(ath,g_at_h);
    SYM(xnh,g_xn_h); SYM(xnl,g_xn_l);
    SYM(wqh,g_wq_h); SYM(wkh,g_wk_h); SYM(wvh,g_wv_h);
    SYM(wih,g_wi_h); SYM(wil,g_wi_l); SYM(wph,g_wp_h); SYM(wpl,g_wp_l);
    SYM(mth,g_mt_h); SYM(mtl,g_mt_l);
    SYM(ao,g_ao); SYM(xnf,g_xnf); SYM(cfold,g_c);

    auto kQ  = mma_gemm<128,1,false,3,true ,false,false>;  // q proj (1-pass, hi)
    auto kK  = mma_gemm<128,1,false,3,true ,false,false>;  // k proj (BM=128, 2/SM)
    auto kV  = mma_gemm<128,1,false,4,true ,false,false>;  // v proj (transposed hi)
    auto kS  = mma_gemm<128,1,true ,3,false,false,true >;  // scores (dual, bf16 out)
    auto kAV = mma_gemm<128,1,false,0,false,true ,false>;  // AV (res, fp32)
    auto kM  = mma_gemm<128,3,false,1,false,false,false>;  // MT = WpT x Wi (3-pass)
    auto kXM = mma_gemm<128,3,false,0,true ,true ,false>;  // out = xn@MT + xn + c
    cudaFuncSetAttribute(kQ,  cudaFuncAttributeMaxDynamicSharedMemorySize, SM_K1_128);
    cudaFuncSetAttribute(kK,  cudaFuncAttributeMaxDynamicSharedMemorySize, SM_K1_128);
    cudaFuncSetAttribute(kV,  cudaFuncAttributeMaxDynamicSharedMemorySize, SM_K1_128);
    cudaFuncSetAttribute(kS,  cudaFuncAttributeMaxDynamicSharedMemorySize, SM_K1_128);
    cudaFuncSetAttribute(kAV, cudaFuncAttributeMaxDynamicSharedMemorySize, SM_K1_128);
    cudaFuncSetAttribute(kM,  cudaFuncAttributeMaxDynamicSharedMemorySize, SM_K3_128);
    cudaFuncSetAttribute(kXM, cudaFuncAttributeMaxDynamicSharedMemorySize, SM_K3_128);

    const float scale = 1.0f / sqrtf(512.0f + 1e-7f);

    static GraphResources R;
    cudaStream_t s1 = R.s1, s2 = R.s2;

    cudaEventRecord(R.eFork, 0);
    cudaStreamWaitEvent(s1, R.eFork, 0);
    cudaStreamWaitEvent(s2, R.eFork, 0);

    // ---- s1: Wk, Wv, FF precompute (MT, c) ----
    transpose_split_kernel<false><<<dim3(DM/32, DM/32), dim3(32,8), 0, s1>>>(Wk, wkh, nullptr, DM, DM);
    cudaEventRecord(R.eWk, s1);
    // s0: LN(kv)
    ln_split_kernel<false,false><<<MKV, 128>>>(key_value, kv_gamma, kv_beta, kvnh, nullptr, nullptr);
    cudaEventRecord(R.eKVN, 0);
    transpose_split_kernel<false><<<dim3(DM/32, DM/32), dim3(32,8), 0, s1>>>(Wv, wvh, nullptr, DM, DM);
    cudaEventRecord(R.eWv, s1);
    // s0: k projection (BM=128, 2 CTAs/SM)
    cudaStreamWaitEvent(0, R.eWk, 0);
    kK<<<dim3(DM/128, MKV/128, 1), 256, SM_K1_128>>>(
        kvnh, nullptr, wkh, nullptr, nullptr, nullptr, nullptr, nullptr,
        bk, nullptr, nullptr, kh, nullptr, DM, DM, DM, DM, 0, 0, 0, 0, 0, 1.0f);

    // s1: FF precompute — split Wi (h/l), transpose Wp (h/l), MT GEMM, c fold
    split2_kernel<<<((size_t)DM*FFD/4 + 255)/256, 256, 0, s1>>>(W_inner, wih, wil, (size_t)DM*FFD/4);
    transpose_split_kernel<true ><<<dim3(DM/32, FFD/32), dim3(32,8), 0, s1>>>(W_proj, wph, wpl, FFD, DM);
    kM<<<dim3(DM/128, DM/128, 1), 256, SM_K3_128, s1>>>(
        wph, wpl, wih, wil, nullptr, nullptr, nullptr, nullptr,
        nullptr, nullptr, nullptr, mth, mtl, DM, FFD, FFD, FFD, 0, 0, 0, 0, 0, 1.0f);
    bias_fold_kernel<<<1, DM, 0, s1>>>(b_inner, W_proj, b_proj, cfold);
    cudaEventRecord(R.eMC, s1);

    // ---- s2: Wq -> LN(q) -> q proj -> pos splits -> v proj ----
    transpose_split_kernel<false><<<dim3(DM/32, DM/32), dim3(32,8), 0, s2>>>(Wq, wqh, nullptr, DM, DM);
    ln_split_kernel<false,false><<<MQ, 128, 0, s2>>>(query, q_gamma, q_beta, qnh, nullptr, nullptr);
    kQ<<<dim3(DM/128, MQ/128, 1), 256, SM_K1_128, s2>>>(
        qnh, nullptr, wqh, nullptr, nullptr, nullptr, nullptr, nullptr,
        bq, nullptr, nullptr, qh, nullptr, DM, DM, DM, DM, 0, 0, 0, 0, 0, 1.0f);
    split_kernel<<<(MQ*DM/4 + 255)/256, 256, 0, s2>>>(query_pos, qph, (size_t)MQ*DM/4);
    split_kernel<<<((size_t)MKV*DM/4 + 255)/256, 256, 0, s2>>>(key_pos, kph, (size_t)MKV*DM/4);
    cudaEventRecord(R.eQside, s2);
    cudaStreamWaitEvent(s2, R.eKVN, 0);
    cudaStreamWaitEvent(s2, R.eWv, 0);
    kV<<<dim3(DM/128, MKV/128, 1), 256, SM_K1_128, s2>>>(
        kvnh, nullptr, wvh, nullptr, nullptr, nullptr, nullptr, nullptr,
        bv, nullptr, nullptr, vth, nullptr, DM, DM, DM, DM, MKV, 0, 0, 0, 0, 1.0f);
    cudaEventRecord(R.eV, s2);

    // ---- s0: scores (dual, bf16-hi out, BM=128) ----
    cudaStreamWaitEvent(0, R.eQside, 0);
    kS<<<dim3(TKV/128, TQ/128, NB), 256, SM_K1_128>>>(
        qh, nullptr, kh, nullptr, qph, nullptr, kph, nullptr,
        nullptr, nullptr, nullptr, sch, nullptr,
        TKV, DM, DM, DM, 0,
        (long long)TQ*DM, (long long)TKV*DM, (long long)TQ*TKV, 0, scale);

    // softmax (bf16 in) -> P hi plane
    softmax_bf16_kernel<<<NB*TQ, 256>>>(sch, ath);

    // AV + residual
    cudaStreamWaitEvent(0, R.eV, 0);
    kAV<<<dim3(DM/128, TQ/128, NB), 256, SM_K1_128>>>(
        ath, nullptr, vth, nullptr, nullptr, nullptr, nullptr, nullptr,
        nullptr, query, ao, nullptr, nullptr,
        DM, TKV, TKV, MKV, 0,
        (long long)TQ*TKV, (long long)TKV, (long long)TQ*DM, (long long)TQ*DM, 1.0f);

    // LN for FF (fp32 + h/l planes)
    ln_split_kernel<true,true><<<MQ, 128>>>(ao, ff_gamma, ff_beta, xnh, xnl, xnf);

    // out = xn @ MT + xn + c   (3-pass)
    cudaStreamWaitEvent(0, R.eMC, 0);
    kXM<<<dim3(DM/128, MQ/128, 1), 256, SM_K3_128>>>(
        xnh, xnl, mth, mtl, nullptr, nullptr, nullptr, nullptr,
        cfold, xnf, out, nullptr, nullptr,
        DM, DM, DM, DM, 0, 0, 0, 0, 0, 1.0f);
}

// round 17
// speedup vs baseline: 1.0734x; 1.0734x over previous
#include <cuda_runtime.h>
#include <cuda_bf16.h>
#include <math.h>
#include <stdint.h>

// ---------------------------------------------------------------------------
// Problem constants
// ---------------------------------------------------------------------------
#define DM   512
#define FFD  2048
#define NB   8
#define TQ   512
#define TKV  4096
#define MQ   (NB*TQ)    // 4096
#define MKV  (NB*TKV)   // 32768

// ---------------------------------------------------------------------------
// Scratch
// ---------------------------------------------------------------------------
#define DEVBF __device__ __align__(256) __nv_bfloat16
DEVBF g_qn_h [(size_t)MQ*DM];                              // LN(query) hi
DEVBF g_kvn_h[(size_t)MKV*DM];                             // LN(kv) hi
DEVBF g_q_h  [(size_t)MQ*DM];                              // q proj hi -> pv hi
DEVBF g_k_h  [(size_t)MKV*DM];                             // k proj hi
DEVBF g_qp_h [(size_t)MQ*DM];                              // query_pos hi -> pv lo
DEVBF g_kp_h [(size_t)MKV*DM];                             // key_pos hi
DEVBF g_vt_h [(size_t)DM*MKV];                             // kvn transposed [DM, MKV]
DEVBF g_sc_h [(size_t)NB*TQ*TKV];                          // bf16 logits
DEVBF g_at_h [(size_t)NB*TQ*TKV];                          // softmax probs hi
DEVBF g_xn_h [(size_t)MQ*DM],   g_xn_l [(size_t)MQ*DM];    // LN(attnout) h/l
DEVBF g_wq_h [(size_t)DM*DM];                              // Wq^T hi
DEVBF g_wk_h [(size_t)DM*DM];
DEVBF g_wv_h [(size_t)DM*DM],   g_wv_l [(size_t)DM*DM];    // Wv^T h/l
DEVBF g_wi_h [(size_t)DM*FFD],  g_wi_l [(size_t)DM*FFD];   // W_inner (row-major) h/l
DEVBF g_wp_h [(size_t)DM*FFD],  g_wp_l [(size_t)DM*FFD];   // W_proj^T [512,2048] h/l
DEVBF g_mt_h [(size_t)DM*DM],   g_mt_l [(size_t)DM*DM];    // MT = (Wi@Wp)^T h/l
__device__ float g_c[DM];                      // folded bias: b_inner@Wp + b_proj
__device__ float g_ao [(size_t)MQ*DM];         // attn out + residual
__device__ float g_xnf[(size_t)MQ*DM];         // LN(attnout) fp32

// ---------------------------------------------------------------------------
// helpers
// ---------------------------------------------------------------------------
__device__ __forceinline__ uint32_t smem_u32(const void* p) {
    uint32_t a;
    asm("{ .reg .u64 t; cvta.to.shared.u64 t, %1; cvt.u32.u64 %0, t; }"
        : "=r"(a) : "l"(p));
    return a;
}
__device__ __forceinline__ void ldm4(uint32_t* r, uint32_t addr) {
    asm volatile("ldmatrix.sync.aligned.m8n8.x4.shared.b16 {%0,%1,%2,%3}, [%4];"
        : "=r"(r[0]), "=r"(r[1]), "=r"(r[2]), "=r"(r[3]) : "r"(addr));
}
__device__ __forceinline__ void mma_bf16(float* c, const uint32_t* a,
                                         uint32_t b0, uint32_t b1) {
    asm volatile(
        "mma.sync.aligned.m16n8k16.row.col.f32.bf16.bf16.f32 "
        "{%0,%1,%2,%3}, {%4,%5,%6,%7}, {%8,%9}, {%0,%1,%2,%3};"
        : "+f"(c[0]), "+f"(c[1]), "+f"(c[2]), "+f"(c[3])
        : "r"(a[0]), "r"(a[1]), "r"(a[2]), "r"(a[3]), "r"(b0), "r"(b1));
}
__device__ __forceinline__ void bsplit(float x, __nv_bfloat16& h, __nv_bfloat16& l) {
    h = __float2bfloat16(x);
    l = __float2bfloat16(x - __bfloat162float(h));
}
#define CPA(dst, src) \
    asm volatile("cp.async.cg.shared.global [%0], [%1], 16;" :: "r"(dst), "l"(src))
#define CPCOMMIT() asm volatile("cp.async.commit_group;" ::: "memory")
#define CPWAIT(n)  asm volatile("cp.async.wait_group %0;" :: "n"(n) : "memory")

#define ROWB   80      // bytes per smem row (32 bf16 + pad), conflict-free ldmatrix
#define NSTG   3

// ---------------------------------------------------------------------------
// bf16 MMA GEMM.
//   NPASS: 1 = hh;  3 = hh + lh + hl (fp32-grade)
//   OUT_MODE: 0=fp32 C, 1=bf16 h/l planes (batched), 3=bf16 hi plane (batched)
// ---------------------------------------------------------------------------
template<int BM, int NPASS, bool DUAL, int OUT_MODE, bool HAS_BIAS, bool HAS_RES, bool HAS_SCALE>
__global__ void __launch_bounds__(BM*2, (BM==128 && NPASS==1) ? 2 : 1)
mma_gemm(const __nv_bfloat16* __restrict__ Ah, const __nv_bfloat16* __restrict__ Al,
         const __nv_bfloat16* __restrict__ Bh, const __nv_bfloat16* __restrict__ Bl,
         const __nv_bfloat16* __restrict__ A2h, const __nv_bfloat16* __restrict__ A2l,
         const __nv_bfloat16* __restrict__ B2h, const __nv_bfloat16* __restrict__ B2l,
         const float* __restrict__ bias, const float* __restrict__ res,
         float* __restrict__ Cf, __nv_bfloat16* __restrict__ Ch, __nv_bfloat16* __restrict__ Cl,
         int N, int K, int lda, int ldb, int ldct,
         long long zA, long long zB, long long zC, long long zRes, float scale)
{
    constexpr int PLA = (NPASS >= 2) ? 2 : 1;
    constexpr int PLB = (NPASS == 3) ? 2 : 1;
    constexpr int PA = BM * ROWB;
    constexpr int PB = 128 * ROWB;
    constexpr int STAGE = PLA * PA + PLB * PB;

    extern __shared__ char dsm[];
    const uint32_t sb = smem_u32(dsm);
    const int t = threadIdx.x, wid = t >> 5, lane = t & 31;
    const int wm = wid >> 2, wn = wid & 3;

    const long long bz = blockIdx.z;
    Ah += bz * zA; Bh += bz * zB;
    if (NPASS >= 2) Al += bz * zA;
    if (NPASS == 3) Bl += bz * zB;
    if (DUAL) { A2h += bz * zA; B2h += bz * zB; }
    if (HAS_RES) res += bz * zRes;
    if (OUT_MODE == 0) Cf += bz * zC;
    if (OUT_MODE == 3) Ch += bz * zC;
    if (OUT_MODE == 1) { Ch += bz * zC; Cl += bz * zC; }

    const int m0 = blockIdx.y * BM;
    const int n0 = blockIdx.x * 128;

    float acc[4][4][4];
    #pragma unroll
    for (int i = 0; i < 4; i++)
        #pragma unroll
        for (int j = 0; j < 4; j++)
            #pragma unroll
            for (int e = 0; e < 4; e++) acc[i][j][e] = 0.0f;

    const int r8 = lane & 7, sel = lane >> 3;
    const uint32_t aOff = (uint32_t)((wm * 64 + (sel & 1) * 8 + r8) * ROWB + ((sel >> 1) * 8) * 2);
    const uint32_t bOff = (uint32_t)((wn * 32 + (sel >> 1) * 8 + r8) * ROWB + ((sel & 1) * 8) * 2);

    const int lrow = t >> 1;
    const int lcol = (t & 1) * 32;

    const int kt = K / 32;
    const int nt = DUAL ? 2 * kt : kt;

#define CPLOAD(ii, stg_) do {                                                    \
        const int pr_ = (DUAL && (ii) >= kt) ? 1 : 0;                            \
        const int k0_ = ((ii) - pr_ * kt) * 32;                                  \
        const uint32_t sd = sb + (stg_) * STAGE + lrow * ROWB + lcol;            \
        const char* gA = (const char*)((pr_ ? A2h : Ah) + (size_t)(m0 + lrow) * lda + k0_) + lcol; \
        CPA(sd, gA);  CPA(sd + 16, gA + 16);                                     \
        if (NPASS >= 2) {                                                        \
            const char* ga = (const char*)((pr_ ? A2h : Al) + (size_t)(m0 + lrow) * lda + k0_) + lcol; \
            CPA(sd + PA, ga);  CPA(sd + PA + 16, ga + 16);                       \
        }                                                                        \
        if (t < 256) {                                                           \
            const char* gB = (const char*)((pr_ ? B2h : Bh) + (size_t)(n0 + lrow) * ldb + k0_) + lcol; \
            CPA(sd + PLA * PA, gB);  CPA(sd + PLA * PA + 16, gB + 16);           \
            if (NPASS == 3) {                                                    \
                const char* gb = (const char*)((pr_ ? B2h : Bl) + (size_t)(n0 + lrow) * ldb + k0_) + lcol; \
                CPA(sd + PLA * PA + PB, gb);  CPA(sd + PLA * PA + PB + 16, gb + 16); \
            }                                                                    \
        }                                                                        \
        CPCOMMIT();                                                              \
    } while (0)

    CPLOAD(0, 0);
    CPLOAD(1, 1);

    int stg = 0;
    #pragma unroll 1
    for (int tt = 0; tt < nt; ++tt) {
        if (tt + 1 < nt) CPWAIT(1); else CPWAIT(0);
        __syncthreads();
        if (tt + 2 < nt) {
            const int ns = (stg + 2 >= NSTG) ? stg + 2 - NSTG : stg + 2;
            CPLOAD(tt + 2, ns);
        }

        const uint32_t sbase = sb + stg * STAGE;
        #pragma unroll
        for (int ks = 0; ks < 2; ++ks) {
            const uint32_t kso = ks * 32;
            uint32_t bh[2][4], bl[2][4];
            #pragma unroll
            for (int bi = 0; bi < 2; bi++) {
                ldm4(bh[bi], sbase + PLA * PA + bOff + bi * (16 * ROWB) + kso);
                if (NPASS == 3)
                    ldm4(bl[bi], sbase + PLA * PA + PB + bOff + bi * (16 * ROWB) + kso);
            }
            #pragma unroll
            for (int mi = 0; mi < 4; mi++) {
                uint32_t ah[4], al[4];
                ldm4(ah, sbase + aOff + mi * (16 * ROWB) + kso);
                if (NPASS >= 2)
                    ldm4(al, sbase + PA + aOff + mi * (16 * ROWB) + kso);
                #pragma unroll
                for (int ni = 0; ni < 4; ni++) {
                    const int bi = ni >> 1, sub = (ni & 1) * 2;
                    mma_bf16(acc[mi][ni], ah, bh[bi][sub], bh[bi][sub + 1]);      // hh
                    if (NPASS >= 2)
                        mma_bf16(acc[mi][ni], al, bh[bi][sub], bh[bi][sub + 1]);  // lh
                    if (NPASS == 3)
                        mma_bf16(acc[mi][ni], ah, bl[bi][sub], bl[bi][sub + 1]);  // hl
                }
            }
        }
        stg = (stg + 1 == NSTG) ? 0 : stg + 1;
    }
#undef CPLOAD

    // ---------------- epilogue ----------------
    const int qr = lane >> 2;
    const int qc = (lane & 3) * 2;

    #pragma unroll
    for (int mi = 0; mi < 4; mi++)
        #pragma unroll
        for (int ni = 0; ni < 4; ni++) {
            const int row = m0 + wm * 64 + mi * 16 + qr;
            const int col = n0 + wn * 32 + ni * 8 + qc;
            float2 bb = make_float2(0.f, 0.f);
            if (HAS_BIAS) bb = *(const float2*)(bias + col);
            #pragma unroll
            for (int h = 0; h < 2; h++) {
                const int rr = row + h * 8;
                float2 o = make_float2(acc[mi][ni][h * 2], acc[mi][ni][h * 2 + 1]);
                if (HAS_SCALE) { o.x *= scale; o.y *= scale; }
                if (HAS_BIAS)  { o.x += bb.x; o.y += bb.y; }
                if (OUT_MODE == 0) {
                    if (HAS_RES) {
                        float2 rv = *(const float2*)(res + (size_t)rr * N + col);
                        o.x += rv.x; o.y += rv.y;
                    }
                    *(float2*)(Cf + (size_t)rr * N + col) = o;
                } else if (OUT_MODE == 1) {
                    __nv_bfloat16 h0, l0, h1, l1;
                    bsplit(o.x, h0, l0);
                    bsplit(o.y, h1, l1);
                    __nv_bfloat162 ph; ph.x = h0; ph.y = h1;
                    __nv_bfloat162 pl; pl.x = l0; pl.y = l1;
                    *(__nv_bfloat162*)(Ch + (size_t)rr * N + col) = ph;
                    *(__nv_bfloat162*)(Cl + (size_t)rr * N + col) = pl;
                } else { // OUT_MODE == 3
                    __nv_bfloat162 ph;
                    ph.x = __float2bfloat16(o.x);
                    ph.y = __float2bfloat16(o.y);
                    *(__nv_bfloat162*)(Ch + (size_t)rr * N + col) = ph;
                }
            }
        }
}

// ---------------------------------------------------------------------------
// LayerNorm (D=512) -> bf16 hi plane [+ lo plane] [+ fp32]
// ---------------------------------------------------------------------------
template<bool LO, bool F32OUT>
__global__ void ln_split_kernel(const float* __restrict__ x,
                                const float* __restrict__ g,
                                const float* __restrict__ b,
                                __nv_bfloat16* __restrict__ yh,
                                __nv_bfloat16* __restrict__ yl,
                                float* __restrict__ yf)
{
    __shared__ float sh[8];
    const size_t row = blockIdx.x;
    const int t = threadIdx.x;

    float4 v = ((const float4*)(x + row * DM))[t];
    float s  = v.x + v.y + v.z + v.w;
    float sq = v.x*v.x + v.y*v.y + v.z*v.z + v.w*v.w;
    #pragma unroll
    for (int o = 16; o > 0; o >>= 1) {
        s  += __shfl_down_sync(0xffffffffu, s,  o);
        sq += __shfl_down_sync(0xffffffffu, sq, o);
    }
    if ((t & 31) == 0) { sh[t >> 5] = s; sh[4 + (t >> 5)] = sq; }
    __syncthreads();
    const float S  = sh[0] + sh[1] + sh[2] + sh[3];
    const float SQ = sh[4] + sh[5] + sh[6] + sh[7];
    const float mu = S * (1.0f / DM);
    const float var = SQ * (1.0f / DM) - mu * mu;
    const float r = rsqrtf(var + 1e-6f);

    const float4 gg = ((const float4*)g)[t];
    const float4 bb = ((const float4*)b)[t];
    float o[4];
    o[0] = (v.x - mu) * r * gg.x + bb.x;
    o[1] = (v.y - mu) * r * gg.y + bb.y;
    o[2] = (v.z - mu) * r * gg.z + bb.z;
    o[3] = (v.w - mu) * r * gg.w + bb.w;

    __nv_bfloat16 h[4], l[4];
    #pragma unroll
    for (int j = 0; j < 4; j++) bsplit(o[j], h[j], l[j]);
    *(uint2*)(yh + row * DM + t * 4) = *(uint2*)h;
    if (LO) *(uint2*)(yl + row * DM + t * 4) = *(uint2*)l;
    if (F32OUT) *(float4*)(yf + row * DM + t * 4) = make_float4(o[0], o[1], o[2], o[3]);
}

// ---------------------------------------------------------------------------
// Elementwise fp32 -> bf16 hi plane (pos tensors)
// ---------------------------------------------------------------------------
__global__ void split_kernel(const float* __restrict__ x,
                             __nv_bfloat16* __restrict__ yh, size_t n4)
{
    const size_t i = (size_t)blockIdx.x * blockDim.x + threadIdx.x;
    if (i >= n4) return;
    float4 v = ((const float4*)x)[i];
    __nv_bfloat16 h[4];
    h[0] = __float2bfloat16(v.x); h[1] = __float2bfloat16(v.y);
    h[2] = __float2bfloat16(v.z); h[3] = __float2bfloat16(v.w);
    *(uint2*)(yh + i * 4) = *(uint2*)h;
}

// Elementwise fp32 -> bf16 hi + lo planes (W_inner)
__global__ void split2_kernel(const float* __restrict__ x,
                              __nv_bfloat16* __restrict__ yh,
                              __nv_bfloat16* __restrict__ yl, size_t n4)
{
    const size_t i = (size_t)blockIdx.x * blockDim.x + threadIdx.x;
    if (i >= n4) return;
    float4 v = ((const float4*)x)[i];
    __nv_bfloat16 h[4], l[4];
    bsplit(v.x, h[0], l[0]); bsplit(v.y, h[1], l[1]);
    bsplit(v.z, h[2], l[2]); bsplit(v.w, h[3], l[3]);
    *(uint2*)(yh + i * 4) = *(uint2*)h;
    *(uint2*)(yl + i * 4) = *(uint2*)l;
}

// ---------------------------------------------------------------------------
// W [K,N] fp32 -> WT hi [N,K] bf16 [+ lo]
// ---------------------------------------------------------------------------
template<bool LO>
__global__ void transpose_split_kernel(const float* __restrict__ W,
                                       __nv_bfloat16* __restrict__ Th,
                                       __nv_bfloat16* __restrict__ Tl,
                                       int K, int N)
{
    __shared__ float tile[32][33];
    const int n0 = blockIdx.x * 32, k0 = blockIdx.y * 32;
    const int tx = threadIdx.x, ty = threadIdx.y;
    #pragma unroll
    for (int i = 0; i < 32; i += 8)
        tile[ty + i][tx] = W[(size_t)(k0 + ty + i) * N + n0 + tx];
    __syncthreads();
    #pragma unroll
    for (int i = 0; i < 32; i += 8) {
        float v = tile[tx][ty + i];
        __nv_bfloat16 h, l;
        bsplit(v, h, l);
        Th[(size_t)(n0 + ty + i) * K + k0 + tx] = h;
        if (LO) Tl[(size_t)(n0 + ty + i) * K + k0 + tx] = l;
    }
}

// ---------------------------------------------------------------------------
// bf16 transpose: X [R,C] -> Y [C,R]   (kvn -> kvnT)
// ---------------------------------------------------------------------------
__global__ void transpose_bf16_kernel(const __nv_bfloat16* __restrict__ X,
                                      __nv_bfloat16* __restrict__ Y,
                                      int R, int C)
{
    __shared__ __nv_bfloat16 tile[32][33];
    const int c0 = blockIdx.x * 32, r0 = blockIdx.y * 32;
    const int tx = threadIdx.x, ty = threadIdx.y;   // block (32,8)
    #pragma unroll
    for (int i = 0; i < 32; i += 8)
        tile[ty + i][tx] = X[(size_t)(r0 + ty + i) * C + c0 + tx];
    __syncthreads();
    #pragma unroll
    for (int i = 0; i < 32; i += 8)
        Y[(size_t)(c0 + ty + i) * R + r0 + tx] = tile[tx][ty + i];
}

// ---------------------------------------------------------------------------
// c = b_inner @ W_proj + b_proj
// ---------------------------------------------------------------------------
__global__ void bias_fold_kernel(const float* __restrict__ bi,
                                 const float* __restrict__ Wp,
                                 const float* __restrict__ bp,
                                 float* __restrict__ c)
{
    const int j = threadIdx.x;  // 512 threads
    float s = bp[j];
    for (int k = 0; k < FFD; k++) s += bi[k] * Wp[(size_t)k * DM + j];
    c[j] = s;
}

// ---------------------------------------------------------------------------
// Row softmax over TKV=4096, bf16 logits in -> bf16 probs out
// ---------------------------------------------------------------------------
__global__ void softmax_bf16_kernel(const __nv_bfloat16* __restrict__ S,
                                    __nv_bfloat16* __restrict__ Ah)
{
    __shared__ float sh[16];
    const size_t row = blockIdx.x;
    const __nv_bfloat16* p = S + row * (size_t)TKV;
    const int t = threadIdx.x;

    float v[16];
    #pragma unroll
    for (int i = 0; i < 4; i++) {
        uint2 u = ((const uint2*)p)[t + 256 * i];
        __nv_bfloat162 a = *(__nv_bfloat162*)&u.x;
        __nv_bfloat162 b = *(__nv_bfloat162*)&u.y;
        v[i*4+0] = __bfloat162float(a.x); v[i*4+1] = __bfloat162float(a.y);
        v[i*4+2] = __bfloat162float(b.x); v[i*4+3] = __bfloat162float(b.y);
    }

    float mx = -3.4e38f;
    #pragma unroll
    for (int i = 0; i < 16; i++) mx = fmaxf(mx, v[i]);
    #pragma unroll
    for (int o = 16; o > 0; o >>= 1) mx = fmaxf(mx, __shfl_xor_sync(0xffffffffu, mx, o));
    if ((t & 31) == 0) sh[t >> 5] = mx;
    __syncthreads();
    float m = sh[0];
    #pragma unroll
    for (int i = 1; i < 8; i++) m = fmaxf(m, sh[i]);

    float s = 0.0f;
    #pragma unroll
    for (int i = 0; i < 16; i++) { v[i] = __expf(v[i] - m); s += v[i]; }
    #pragma unroll
    for (int o = 16; o > 0; o >>= 1) s += __shfl_xor_sync(0xffffffffu, s, o);
    if ((t & 31) == 0) sh[8 + (t >> 5)] = s;
    __syncthreads();
    float tot = 0.0f;
    #pragma unroll
    for (int i = 0; i < 8; i++) tot += sh[8 + i];
    const float inv = 1.0f / tot;

    #pragma unroll
    for (int i = 0; i < 4; i++) {
        __nv_bfloat16 h[4];
        h[0] = __float2bfloat16(v[i*4+0] * inv);
        h[1] = __float2bfloat16(v[i*4+1] * inv);
        h[2] = __float2bfloat16(v[i*4+2] * inv);
        h[3] = __float2bfloat16(v[i*4+3] * inv);
        *(uint2*)(Ah + row * (size_t)TKV + (t + 256 * i) * 4) = *(uint2*)h;
    }
}

// ---------------------------------------------------------------------------
// Launcher. V path reassociated: result = (P @ kvn) @ Wv + bv.
// Streams/events are statics created once on the first (uncaptured) call.
// ---------------------------------------------------------------------------
#define SYM(p, s) cudaGetSymbolAddress((void**)&p, s)
#define SM_K1_128 (NSTG * (128*ROWB + 128*ROWB))              // 61440
#define SM_K3_128 (NSTG * 2 * (128*ROWB + 128*ROWB))          // 122880

namespace {
struct GraphResources {
    cudaStream_t s1, s2;
    cudaEvent_t eFork, eWk, eKVN, eWv, eQside, eV, eMC;
    GraphResources() {
        cudaStreamCreateWithFlags(&s1, cudaStreamNonBlocking);
        cudaStreamCreateWithFlags(&s2, cudaStreamNonBlocking);
        cudaEventCreateWithFlags(&eFork, cudaEventDisableTiming);
        cudaEventCreateWithFlags(&eWk,   cudaEventDisableTiming);
        cudaEventCreateWithFlags(&eKVN,  cudaEventDisableTiming);
        cudaEventCreateWithFlags(&eWv,   cudaEventDisableTiming);
        cudaEventCreateWithFlags(&eQside,cudaEventDisableTiming);
        cudaEventCreateWithFlags(&eV,    cudaEventDisableTiming);
        cudaEventCreateWithFlags(&eMC,   cudaEventDisableTiming);
    }
};
} // namespace

extern "C" void kernel_launch(void* const* d_in, const int* in_sizes, int n_in,
                              void* d_out, int out_size)
{
    (void)in_sizes; (void)n_in; (void)out_size;
    const float* query     = (const float*)d_in[0];
    const float* key_value = (const float*)d_in[1];
    const float* query_pos = (const float*)d_in[2];
    const float* key_pos   = (const float*)d_in[3];
    const float* q_gamma   = (const float*)d_in[4];
    const float* q_beta    = (const float*)d_in[5];
    const float* kv_gamma  = (const float*)d_in[6];
    const float* kv_beta   = (const float*)d_in[7];
    const float* Wq        = (const float*)d_in[8];
    const float* bq        = (const float*)d_in[9];
    const float* Wk        = (const float*)d_in[10];
    const float* bk        = (const float*)d_in[11];
    const float* Wv        = (const float*)d_in[12];
    const float* bv        = (const float*)d_in[13];
    const float* ff_gamma  = (const float*)d_in[14];
    const float* ff_beta   = (const float*)d_in[15];
    const float* W_inner   = (const float*)d_in[16];
    const float* b_inner   = (const float*)d_in[17];
    const float* W_proj    = (const float*)d_in[18];
    const float* b_proj    = (const float*)d_in[19];
    float* out = (float*)d_out;

    __nv_bfloat16 *qnh,*kvnh,*qh,*kh,*qph,*kph,*vth,*sch,*ath,*xnh,*xnl;
    __nv_bfloat16 *wqh,*wkh,*wvh,*wvl,*wih,*wil,*wph,*wpl,*mth,*mtl;
    float *ao,*xnf,*cfold;
    SYM(qnh,g_qn_h); SYM(kvnh,g_kvn_h);
    SYM(qh,g_q_h); SYM(kh,g_k_h);
    SYM(qph,g_qp_h); SYM(kph,g_kp_h);
    SYM(vth,g_vt_h); SYM(sch,g_sc_h); SYM(ath,g_at_h);
    SYM(xnh,g_xn_h); SYM(xnl,g_xn_l);
    SYM(wqh,g_wq_h); SYM(wkh,g_wk_h); SYM(wvh,g_wv_h); SYM(wvl,g_wv_l);
    SYM(wih,g_wi_h); SYM(wil,g_wi_l); SYM(wph,g_wp_h); SYM(wpl,g_wp_l);
    SYM(mth,g_mt_h); SYM(mtl,g_mt_l);
    SYM(ao,g_ao); SYM(xnf,g_xnf); SYM(cfold,g_c);
    // pv planes reuse q / qpos buffers (dead after scores)
    __nv_bfloat16 *pvh = qh, *pvl = qph;

    auto kQ  = mma_gemm<128,1,false,3,true ,false,false>;  // q/k proj (1-pass, hi)
    auto kS  = mma_gemm<128,1,true ,3,false,false,true >;  // scores (dual, bf16 out)
    auto kPV = mma_gemm<128,1,false,1,false,false,false>;  // pv = P @ kvnT (h/l out, batched)
    auto kM  = mma_gemm<128,3,false,1,false,false,false>;  // MT = WpT x Wi (3-pass)
    auto kXM = mma_gemm<128,3,false,0,true ,true ,false>;  // 3-pass + bias + res -> fp32
    cudaFuncSetAttribute(kQ,  cudaFuncAttributeMaxDynamicSharedMemorySize, SM_K1_128);
    cudaFuncSetAttribute(kS,  cudaFuncAttributeMaxDynamicSharedMemorySize, SM_K1_128);
    cudaFuncSetAttribute(kPV, cudaFuncAttributeMaxDynamicSharedMemorySize, SM_K1_128);
    cudaFuncSetAttribute(kM,  cudaFuncAttributeMaxDynamicSharedMemorySize, SM_K3_128);
    cudaFuncSetAttribute(kXM, cudaFuncAttributeMaxDynamicSharedMemorySize, SM_K3_128);

    const float scale = 1.0f / sqrtf(512.0f + 1e-7f);

    static GraphResources R;
    cudaStream_t s1 = R.s1, s2 = R.s2;

    cudaEventRecord(R.eFork, 0);
    cudaStreamWaitEvent(s1, R.eFork, 0);
    cudaStreamWaitEvent(s2, R.eFork, 0);

    // ---- s1: Wk, Wv, FF precompute (MT, c) ----
    transpose_split_kernel<false><<<dim3(DM/32, DM/32), dim3(32,8), 0, s1>>>(Wk, wkh, nullptr, DM, DM);
    cudaEventRecord(R.eWk, s1);
    // s0: LN(kv)
    ln_split_kernel<false,false><<<MKV, 128>>>(key_value, kv_gamma, kv_beta, kvnh, nullptr, nullptr);
    cudaEventRecord(R.eKVN, 0);
    transpose_split_kernel<true ><<<dim3(DM/32, DM/32), dim3(32,8), 0, s1>>>(Wv, wvh, wvl, DM, DM);
    cudaEventRecord(R.eWv, s1);
    // s0: k projection
    cudaStreamWaitEvent(0, R.eWk, 0);
    kQ<<<dim3(DM/128, MKV/128, 1), 256, SM_K1_128>>>(
        kvnh, nullptr, wkh, nullptr, nullptr, nullptr, nullptr, nullptr,
        bk, nullptr, nullptr, kh, nullptr, DM, DM, DM, DM, 0, 0, 0, 0, 0, 1.0f);

    // s1: FF precompute — split Wi (h/l), transpose Wp (h/l), MT GEMM, c fold
    split2_kernel<<<((size_t)DM*FFD/4 + 255)/256, 256, 0, s1>>>(W_inner, wih, wil, (size_t)DM*FFD/4);
    transpose_split_kernel<true ><<<dim3(DM/32, FFD/32), dim3(32,8), 0, s1>>>(W_proj, wph, wpl, FFD, DM);
    kM<<<dim3(DM/128, DM/128, 1), 256, SM_K3_128, s1>>>(
        wph, wpl, wih, wil, nullptr, nullptr, nullptr, nullptr,
        nullptr, nullptr, nullptr, mth, mtl, DM, FFD, FFD, FFD, 0, 0, 0, 0, 0, 1.0f);
    bias_fold_kernel<<<1, DM, 0, s1>>>(b_inner, W_proj, b_proj, cfold);
    cudaEventRecord(R.eMC, s1);

    // ---- s2: Wq -> LN(q) -> q proj -> pos splits -> kvn transpose ----
    transpose_split_kernel<false><<<dim3(DM/32, DM/32), dim3(32,8), 0, s2>>>(Wq, wqh, nullptr, DM, DM);
    ln_split_kernel<false,false><<<MQ, 128, 0, s2>>>(query, q_gamma, q_beta, qnh, nullptr, nullptr);
    kQ<<<dim3(DM/128, MQ/128, 1), 256, SM_K1_128, s2>>>(
        qnh, nullptr, wqh, nullptr, nullptr, nullptr, nullptr, nullptr,
        bq, nullptr, nullptr, qh, nullptr, DM, DM, DM, DM, 0, 0, 0, 0, 0, 1.0f);
    split_kernel<<<(MQ*DM/4 + 255)/256, 256, 0, s2>>>(query_pos, qph, (size_t)MQ*DM/4);
    split_kernel<<<((size_t)MKV*DM/4 + 255)/256, 256, 0, s2>>>(key_pos, kph, (size_t)MKV*DM/4);
    cudaEventRecord(R.eQside, s2);
    // kvnT [DM, MKV] (replaces the whole v-projection GEMM)
    cudaStreamWaitEvent(s2, R.eKVN, 0);
    transpose_bf16_kernel<<<dim3(DM/32, MKV/32), dim3(32,8), 0, s2>>>(kvnh, vth, MKV, DM);
    cudaEventRecord(R.eV, s2);

    // ---- s0: scores (dual, bf16-hi out) ----
    cudaStreamWaitEvent(0, R.eQside, 0);
    kS<<<dim3(TKV/128, TQ/128, NB), 256, SM_K1_128>>>(
        qh, nullptr, kh, nullptr, qph, nullptr, kph, nullptr,
        nullptr, nullptr, nullptr, sch, nullptr,
        TKV, DM, DM, DM, 0,
        (long long)TQ*DM, (long long)TKV*DM, (long long)TQ*TKV, 0, scale);

    // softmax (bf16 in) -> P hi plane
    softmax_bf16_kernel<<<NB*TQ, 256>>>(sch, ath);

    // pv = P @ kvnT  (batched; h/l planes into dead q/qpos buffers)
    cudaStreamWaitEvent(0, R.eV, 0);
    kPV<<<dim3(DM/128, TQ/128, NB), 256, SM_K1_128>>>(
        ath, nullptr, vth, nullptr, nullptr, nullptr, nullptr, nullptr,
        nullptr, nullptr, nullptr, pvh, pvl,
        DM, TKV, TKV, MKV, 0,
        (long long)TQ*TKV, (long long)TKV, (long long)TQ*DM, 0, 1.0f);

    // ao = pv @ Wv^T + bv + query   (3-pass; exact bias passthrough since ΣP=1)
    cudaStreamWaitEvent(0, R.eWv, 0);
    kXM<<<dim3(DM/128, MQ/128, 1), 256, SM_K3_128>>>(
        pvh, pvl, wvh, wvl, nullptr, nullptr, nullptr, nullptr,
        bv, query, ao, nullptr, nullptr,
        DM, DM, DM, DM, 0, 0, 0, 0, 0, 1.0f);

    // LN for FF (fp32 + h/l planes)
    ln_split_kernel<true,true><<<MQ, 128>>>(ao, ff_gamma, ff_beta, xnh, xnl, xnf);

    // out = xn @ MT + xn + c   (3-pass)
    cudaStreamWaitEvent(0, R.eMC, 0);
    kXM<<<dim3(DM/128, MQ/128, 1), 256, SM_K3_128>>>(
        xnh, xnl, mth, mtl, nullptr, nullptr, nullptr, nullptr,
        cfold, xnf, out, nullptr, nullptr,
        DM, DM, DM, DM, 0, 0, 0, 0, 0, 1.0f);
}